// round 1
// baseline (speedup 1.0000x reference)
#include <cuda_runtime.h>
#include <math.h>

// Problem constants
#define Bz 32
#define Sz 512
#define Hz 1024
#define Lz 2
#define WD 4
#define Mz (Bz*Sz)        // 16384 rows
#define N2 (2*Hz)         // 2048 proj cols

// Scratch (allocation-free: device globals)
__device__ float g_fo[(size_t)Mz*Hz];     // forward stream state
__device__ float g_bo[(size_t)Mz*Hz];     // backward stream state
__device__ float g_x [(size_t)Mz*Hz];     // current activation x
__device__ float g_proj[(size_t)Mz*N2];   // GEMM output (proj)

// ---------------------------------------------------------------------------
// init: g_fo = g_bo = inputs
// ---------------------------------------------------------------------------
__global__ void init_kernel(const float* __restrict__ inp) {
    size_t i = (size_t)blockIdx.x * blockDim.x + threadIdx.x;
    float4 v = ((const float4*)inp)[i];
    ((float4*)g_fo)[i] = v;
    ((float4*)g_bo)[i] = v;
}

// ---------------------------------------------------------------------------
// window sum:
//  fw: x[b,t] = sum_{k=0..4} w[k] * seqrow(t+k-4)   (front pad rows for <0)
//  bw: x[b,t] = sum_{k=0..4} w[k] * seqrow(t+k)     (back pad rows for >=S)
//  front pad = fw_pad[l], back pad = bw_pad[l] for BOTH directions (ref quirk)
// ---------------------------------------------------------------------------
__global__ void wsum_kernel(const float* __restrict__ pf,
                            const float* __restrict__ pb,
                            const float* __restrict__ w5, int dir) {
    const float* o = dir ? g_bo : g_fo;
    int m  = blockIdx.x;          // b*S + t
    int t  = m & (Sz - 1);
    int h4 = threadIdx.x;         // 0..255 (float4 lanes over H)
    float4 acc = make_float4(0.f, 0.f, 0.f, 0.f);
#pragma unroll
    for (int k = 0; k <= WD; k++) {
        int p = t + k + (dir ? 0 : -WD);   // sequence position
        const float4* src;
        if (p < 0)          src = (const float4*)(pf + (size_t)(p + WD) * Hz);
        else if (p >= Sz)   src = (const float4*)(pb + (size_t)(p - Sz) * Hz);
        else                src = (const float4*)(o  + (size_t)(m - t + p) * Hz);
        float wk = w5[k];
        float4 v = src[h4];
        acc.x += wk * v.x; acc.y += wk * v.y;
        acc.z += wk * v.z; acc.w += wk * v.w;
    }
    ((float4*)g_x)[(size_t)m * (Hz/4) + h4] = acc;
}

// ---------------------------------------------------------------------------
// sgemm: g_proj[16384,2048] = g_x[16384,1024] @ W[1024,2048]
// 128x128 block tile, 8x8 per thread, BK=8, register prefetch.
// ---------------------------------------------------------------------------
__global__ void __launch_bounds__(256) sgemm_kernel(const float* __restrict__ Bw) {
    const int K = Hz;       // 1024
    const int N = N2;       // 2048
    __shared__ float As[8][128];   // A tile transposed: As[k][m]
    __shared__ float Bs[8][128];   // Bs[k][n]

    int tid  = threadIdx.x;
    int row0 = blockIdx.y * 128;
    int col0 = blockIdx.x * 128;

    int a_row = tid >> 1;            // 0..127
    int a_col = (tid & 1) << 2;      // 0 or 4
    int b_row = tid >> 5;            // 0..7
    int b_col = (tid & 31) << 2;     // 0..124

    int tx = (tid & 15) << 3;        // col within tile
    int ty = (tid >> 4) << 3;        // row within tile

    const float* Aptr = g_x + (size_t)(row0 + a_row) * K + a_col;
    const float* Bptr = Bw  + (size_t)b_row * N + col0 + b_col;

    float acc[8][8];
#pragma unroll
    for (int i = 0; i < 8; i++)
#pragma unroll
        for (int j = 0; j < 8; j++) acc[i][j] = 0.f;

    // prefetch first tiles into registers
    float4 av = *(const float4*)Aptr;
    float4 bv = *(const float4*)Bptr;

    for (int k0 = 0; k0 < K; k0 += 8) {
        As[a_col + 0][a_row] = av.x;
        As[a_col + 1][a_row] = av.y;
        As[a_col + 2][a_row] = av.z;
        As[a_col + 3][a_row] = av.w;
        *(float4*)&Bs[b_row][b_col] = bv;
        __syncthreads();

        // prefetch next tile while computing this one
        if (k0 + 8 < K) {
            Aptr += 8;
            Bptr += 8 * N;
            av = *(const float4*)Aptr;
            bv = *(const float4*)Bptr;
        }

#pragma unroll
        for (int k = 0; k < 8; k++) {
            float a[8], b[8];
            *(float4*)(a + 0) = *(const float4*)&As[k][ty + 0];
            *(float4*)(a + 4) = *(const float4*)&As[k][ty + 4];
            *(float4*)(b + 0) = *(const float4*)&Bs[k][tx + 0];
            *(float4*)(b + 4) = *(const float4*)&Bs[k][tx + 4];
#pragma unroll
            for (int i = 0; i < 8; i++)
#pragma unroll
                for (int j = 0; j < 8; j++)
                    acc[i][j] += a[i] * b[j];
        }
        __syncthreads();
    }

    // store
#pragma unroll
    for (int i = 0; i < 8; i++) {
        float* crow = g_proj + (size_t)(row0 + ty + i) * N + col0 + tx;
        float4 v0 = make_float4(acc[i][0], acc[i][1], acc[i][2], acc[i][3]);
        float4 v1 = make_float4(acc[i][4], acc[i][5], acc[i][6], acc[i][7]);
        *(float4*)(crow + 0) = v0;
        *(float4*)(crow + 4) = v1;
    }
}

// ---------------------------------------------------------------------------
// highway combine: x = g*x + (1-g)*relu(nl),
//   nl = proj[:, :H] + b[:H],  g = sigmoid(proj[:, H:] + b[H:])
// In-place on g_x.
// ---------------------------------------------------------------------------
__device__ __forceinline__ float sigm(float z) { return 1.f / (1.f + expf(-z)); }

__global__ void combine_kernel(const float* __restrict__ bias) {
    int m  = blockIdx.x;
    int h4 = threadIdx.x;     // 0..255
    const float4* pr = (const float4*)g_proj + (size_t)m * (N2/4);
    const float4* b4 = (const float4*)bias;
    float4 nl = pr[h4];
    float4 gg = pr[h4 + Hz/4];
    float4 bn = b4[h4];
    float4 bg = b4[h4 + Hz/4];
    float4* xp = (float4*)g_x + (size_t)m * (Hz/4) + h4;
    float4 xv = *xp;

    float g0 = sigm(gg.x + bg.x), g1 = sigm(gg.y + bg.y);
    float g2 = sigm(gg.z + bg.z), g3 = sigm(gg.w + bg.w);
    float n0 = fmaxf(nl.x + bn.x, 0.f), n1 = fmaxf(nl.y + bn.y, 0.f);
    float n2 = fmaxf(nl.z + bn.z, 0.f), n3 = fmaxf(nl.w + bn.w, 0.f);

    xv.x = g0 * xv.x + (1.f - g0) * n0;
    xv.y = g1 * xv.y + (1.f - g1) * n1;
    xv.z = g2 * xv.z + (1.f - g2) * n2;
    xv.w = g3 * xv.w + (1.f - g3) * n3;
    *xp = xv;
}

// ---------------------------------------------------------------------------
// finalize: residual (l>0), update direction state, write output slab
// out layout: [L, B, S, 2H]; fw in [:H], bw in [H:]
// ---------------------------------------------------------------------------
__global__ void finalize_kernel(float* __restrict__ out, int l, int dir) {
    int m  = blockIdx.x;
    int h4 = threadIdx.x;
    float* o = dir ? g_bo : g_fo;
    float4 v = ((float4*)g_x)[(size_t)m * (Hz/4) + h4];
    float4* op = (float4*)o + (size_t)m * (Hz/4) + h4;
    if (l) {
        float4 c = *op;
        v.x += c.x; v.y += c.y; v.z += c.z; v.w += c.w;
    }
    *op = v;
    ((float4*)out)[((size_t)l * Mz + m) * (N2/4) + (size_t)dir * (Hz/4) + h4] = v;
}

// ---------------------------------------------------------------------------
// launch
// ---------------------------------------------------------------------------
extern "C" void kernel_launch(void* const* d_in, const int* in_sizes, int n_in,
                              void* d_out, int out_size) {
    const float* inputs = (const float*)d_in[0];
    // d_in[1] = masks (int32, all ones) — unused by the reference
    const float* fw_pad = (const float*)d_in[2];
    const float* bw_pad = (const float*)d_in[3];
    const float* fw_w   = (const float*)d_in[4];
    const float* bw_w   = (const float*)d_in[5];
    const float* fw_W   = (const float*)d_in[6];
    const float* fw_b   = (const float*)d_in[7];
    const float* bw_W   = (const float*)d_in[8];
    const float* bw_b   = (const float*)d_in[9];
    float* out = (float*)d_out;

    init_kernel<<<(size_t)Mz * Hz / 4 / 256, 256>>>(inputs);

    for (int l = 0; l < Lz; l++) {
        for (int dir = 0; dir < 2; dir++) {
            const float* Wl = (dir ? bw_W : fw_W) + (size_t)l * 2 * Hz * N2;
            const float* bl = (dir ? bw_b : fw_b) + (size_t)l * 2 * N2;
            const float* wv = (dir ? bw_w : fw_w) + (size_t)l * (WD + 1);

            wsum_kernel<<<Mz, 256>>>(fw_pad + (size_t)l * WD * Hz,
                                     bw_pad + (size_t)l * WD * Hz,
                                     wv, dir);
            for (int hw = 0; hw < 2; hw++) {
                sgemm_kernel<<<dim3(N2 / 128, Mz / 128), 256>>>(
                    Wl + (size_t)hw * Hz * N2);
                combine_kernel<<<Mz, 256>>>(bl + (size_t)hw * N2);
            }
            finalize_kernel<<<Mz, 256>>>(out, l, dir);
        }
    }
}

// round 2
// speedup vs baseline: 1.0010x; 1.0010x over previous
#include <cuda_runtime.h>
#include <math.h>

// Problem constants
#define Bz 32
#define Sz 512
#define Hz 1024
#define Lz 2
#define WD 4
#define Mz (Bz*Sz)        // 16384 rows
#define N2 (2*Hz)         // 2048 proj cols

// Scratch (allocation-free: device globals)
__device__ float g_fo[(size_t)Mz*Hz];     // forward stream state
__device__ float g_bo[(size_t)Mz*Hz];     // backward stream state
__device__ float g_x [(size_t)Mz*Hz];     // current activation x
__device__ float g_proj[(size_t)Mz*N2];   // GEMM output (proj)

// ---------------------------------------------------------------------------
// init: g_fo = g_bo = inputs
// ---------------------------------------------------------------------------
__global__ void init_kernel(const float* __restrict__ inp) {
    size_t i = (size_t)blockIdx.x * blockDim.x + threadIdx.x;
    float4 v = ((const float4*)inp)[i];
    ((float4*)g_fo)[i] = v;
    ((float4*)g_bo)[i] = v;
}

// ---------------------------------------------------------------------------
// window sum:
//  fw: x[b,t] = sum_{k=0..4} w[k] * seqrow(t+k-4)   (front pad rows for <0)
//  bw: x[b,t] = sum_{k=0..4} w[k] * seqrow(t+k)     (back pad rows for >=S)
//  front pad = fw_pad[l], back pad = bw_pad[l] for BOTH directions (ref quirk)
// ---------------------------------------------------------------------------
__global__ void wsum_kernel(const float* __restrict__ pf,
                            const float* __restrict__ pb,
                            const float* __restrict__ w5, int dir) {
    const float* o = dir ? g_bo : g_fo;
    int m  = blockIdx.x;          // b*S + t
    int t  = m & (Sz - 1);
    int h4 = threadIdx.x;         // 0..255 (float4 lanes over H)
    float4 acc = make_float4(0.f, 0.f, 0.f, 0.f);
#pragma unroll
    for (int k = 0; k <= WD; k++) {
        int p = t + k + (dir ? 0 : -WD);   // sequence position
        const float4* src;
        if (p < 0)          src = (const float4*)(pf + (size_t)(p + WD) * Hz);
        else if (p >= Sz)   src = (const float4*)(pb + (size_t)(p - Sz) * Hz);
        else                src = (const float4*)(o  + (size_t)(m - t + p) * Hz);
        float wk = w5[k];
        float4 v = src[h4];
        acc.x += wk * v.x; acc.y += wk * v.y;
        acc.z += wk * v.z; acc.w += wk * v.w;
    }
    ((float4*)g_x)[(size_t)m * (Hz/4) + h4] = acc;
}

// ---------------------------------------------------------------------------
// sgemm: g_proj[16384,2048] = g_x[16384,1024] @ W[1024,2048]
// 128x128 block tile, 8x8 per thread, BK=8, register prefetch.
// ---------------------------------------------------------------------------
__global__ void __launch_bounds__(256) sgemm_kernel(const float* __restrict__ Bw) {
    const int K = Hz;       // 1024
    const int N = N2;       // 2048
    __shared__ float As[8][128];   // A tile transposed: As[k][m]
    __shared__ float Bs[8][128];   // Bs[k][n]

    int tid  = threadIdx.x;
    int row0 = blockIdx.y * 128;
    int col0 = blockIdx.x * 128;

    int a_row = tid >> 1;            // 0..127
    int a_col = (tid & 1) << 2;      // 0 or 4
    int b_row = tid >> 5;            // 0..7
    int b_col = (tid & 31) << 2;     // 0..124

    int tx = (tid & 15) << 3;        // col within tile
    int ty = (tid >> 4) << 3;        // row within tile

    const float* Aptr = g_x + (size_t)(row0 + a_row) * K + a_col;
    const float* Bptr = Bw  + (size_t)b_row * N + col0 + b_col;

    float acc[8][8];
#pragma unroll
    for (int i = 0; i < 8; i++)
#pragma unroll
        for (int j = 0; j < 8; j++) acc[i][j] = 0.f;

    // prefetch first tiles into registers
    float4 av = *(const float4*)Aptr;
    float4 bv = *(const float4*)Bptr;

    for (int k0 = 0; k0 < K; k0 += 8) {
        As[a_col + 0][a_row] = av.x;
        As[a_col + 1][a_row] = av.y;
        As[a_col + 2][a_row] = av.z;
        As[a_col + 3][a_row] = av.w;
        *(float4*)&Bs[b_row][b_col] = bv;
        __syncthreads();

        // prefetch next tile while computing this one
        if (k0 + 8 < K) {
            Aptr += 8;
            Bptr += 8 * N;
            av = *(const float4*)Aptr;
            bv = *(const float4*)Bptr;
        }

#pragma unroll
        for (int k = 0; k < 8; k++) {
            float a[8], b[8];
            *(float4*)(a + 0) = *(const float4*)&As[k][ty + 0];
            *(float4*)(a + 4) = *(const float4*)&As[k][ty + 4];
            *(float4*)(b + 0) = *(const float4*)&Bs[k][tx + 0];
            *(float4*)(b + 4) = *(const float4*)&Bs[k][tx + 4];
#pragma unroll
            for (int i = 0; i < 8; i++)
#pragma unroll
                for (int j = 0; j < 8; j++)
                    acc[i][j] += a[i] * b[j];
        }
        __syncthreads();
    }

    // store
#pragma unroll
    for (int i = 0; i < 8; i++) {
        float* crow = g_proj + (size_t)(row0 + ty + i) * N + col0 + tx;
        float4 v0 = make_float4(acc[i][0], acc[i][1], acc[i][2], acc[i][3]);
        float4 v1 = make_float4(acc[i][4], acc[i][5], acc[i][6], acc[i][7]);
        *(float4*)(crow + 0) = v0;
        *(float4*)(crow + 4) = v1;
    }
}

// ---------------------------------------------------------------------------
// highway combine: x = g*x + (1-g)*relu(nl),
//   nl = proj[:, :H] + b[:H],  g = sigmoid(proj[:, H:] + b[H:])
// In-place on g_x.
// ---------------------------------------------------------------------------
__device__ __forceinline__ float sigm(float z) { return 1.f / (1.f + expf(-z)); }

__global__ void combine_kernel(const float* __restrict__ bias) {
    int m  = blockIdx.x;
    int h4 = threadIdx.x;     // 0..255
    const float4* pr = (const float4*)g_proj + (size_t)m * (N2/4);
    const float4* b4 = (const float4*)bias;
    float4 nl = pr[h4];
    float4 gg = pr[h4 + Hz/4];
    float4 bn = b4[h4];
    float4 bg = b4[h4 + Hz/4];
    float4* xp = (float4*)g_x + (size_t)m * (Hz/4) + h4;
    float4 xv = *xp;

    float g0 = sigm(gg.x + bg.x), g1 = sigm(gg.y + bg.y);
    float g2 = sigm(gg.z + bg.z), g3 = sigm(gg.w + bg.w);
    float n0 = fmaxf(nl.x + bn.x, 0.f), n1 = fmaxf(nl.y + bn.y, 0.f);
    float n2 = fmaxf(nl.z + bn.z, 0.f), n3 = fmaxf(nl.w + bn.w, 0.f);

    xv.x = g0 * xv.x + (1.f - g0) * n0;
    xv.y = g1 * xv.y + (1.f - g1) * n1;
    xv.z = g2 * xv.z + (1.f - g2) * n2;
    xv.w = g3 * xv.w + (1.f - g3) * n3;
    *xp = xv;
}

// ---------------------------------------------------------------------------
// finalize: residual (l>0), update direction state, write output slab
// out layout: [L, B, S, 2H]; fw in [:H], bw in [H:]
// ---------------------------------------------------------------------------
__global__ void finalize_kernel(float* __restrict__ out, int l, int dir) {
    int m  = blockIdx.x;
    int h4 = threadIdx.x;
    float* o = dir ? g_bo : g_fo;
    float4 v = ((float4*)g_x)[(size_t)m * (Hz/4) + h4];
    float4* op = (float4*)o + (size_t)m * (Hz/4) + h4;
    if (l) {
        float4 c = *op;
        v.x += c.x; v.y += c.y; v.z += c.z; v.w += c.w;
    }
    *op = v;
    ((float4*)out)[((size_t)l * Mz + m) * (N2/4) + (size_t)dir * (Hz/4) + h4] = v;
}

// ---------------------------------------------------------------------------
// launch
// ---------------------------------------------------------------------------
extern "C" void kernel_launch(void* const* d_in, const int* in_sizes, int n_in,
                              void* d_out, int out_size) {
    const float* inputs = (const float*)d_in[0];
    // d_in[1] = masks (int32, all ones) — unused by the reference
    const float* fw_pad = (const float*)d_in[2];
    const float* bw_pad = (const float*)d_in[3];
    const float* fw_w   = (const float*)d_in[4];
    const float* bw_w   = (const float*)d_in[5];
    const float* fw_W   = (const float*)d_in[6];
    const float* fw_b   = (const float*)d_in[7];
    const float* bw_W   = (const float*)d_in[8];
    const float* bw_b   = (const float*)d_in[9];
    float* out = (float*)d_out;

    init_kernel<<<(size_t)Mz * Hz / 4 / 256, 256>>>(inputs);

    for (int l = 0; l < Lz; l++) {
        for (int dir = 0; dir < 2; dir++) {
            const float* Wl = (dir ? bw_W : fw_W) + (size_t)l * 2 * Hz * N2;
            const float* bl = (dir ? bw_b : fw_b) + (size_t)l * 2 * N2;
            const float* wv = (dir ? bw_w : fw_w) + (size_t)l * (WD + 1);

            wsum_kernel<<<Mz, 256>>>(fw_pad + (size_t)l * WD * Hz,
                                     bw_pad + (size_t)l * WD * Hz,
                                     wv, dir);
            for (int hw = 0; hw < 2; hw++) {
                sgemm_kernel<<<dim3(N2 / 128, Mz / 128), 256>>>(
                    Wl + (size_t)hw * Hz * N2);
                combine_kernel<<<Mz, 256>>>(bl + (size_t)hw * N2);
            }
            finalize_kernel<<<Mz, 256>>>(out, l, dir);
        }
    }
}

// round 4
// speedup vs baseline: 2.9370x; 2.9340x over previous
#include <cuda_runtime.h>
#include <cuda_bf16.h>
#include <math.h>
#include <stdint.h>

// Problem constants
#define Bz 32
#define Sz 512
#define Hz 1024
#define Lz 2
#define WD 4
#define Mz (Bz*Sz)        // 16384 rows
#define N2 (2*Hz)         // 2048 proj cols

#define SW128(off) ((off) ^ (((off) >> 3) & 0x70))

__device__ __forceinline__ uint32_t smem_to_u32(const void* p) {
    uint32_t a;
    asm("{ .reg .u64 t; cvta.to.shared.u64 t, %1; cvt.u32.u64 %0, t; }" : "=r"(a) : "l"(p));
    return a;
}

__device__ __forceinline__ void cpasync16(uint32_t dst, const void* src) {
    asm volatile("cp.async.cg.shared.global [%0], [%1], 16;" :: "r"(dst), "l"(src));
}
#define CP_COMMIT() asm volatile("cp.async.commit_group;" ::: "memory")
#define CP_WAIT(n)  asm volatile("cp.async.wait_group %0;" :: "n"(n) : "memory")

__device__ __forceinline__ void ldsm4(uint32_t* r, uint32_t addr) {
    asm volatile("ldmatrix.sync.aligned.m8n8.x4.shared.b16 {%0,%1,%2,%3}, [%4];"
        : "=r"(r[0]), "=r"(r[1]), "=r"(r[2]), "=r"(r[3]) : "r"(addr));
}

__device__ __forceinline__ void mma16816(float* c, const uint32_t* a, const uint32_t* b) {
    asm volatile("mma.sync.aligned.m16n8k16.row.col.f32.bf16.bf16.f32 "
        "{%0,%1,%2,%3}, {%4,%5,%6,%7}, {%8,%9}, {%0,%1,%2,%3};"
        : "+f"(c[0]), "+f"(c[1]), "+f"(c[2]), "+f"(c[3])
        : "r"(a[0]), "r"(a[1]), "r"(a[2]), "r"(a[3]), "r"(b[0]), "r"(b[1]));
}

// ---------------------------------------------------------------------------
// Scratch (device globals, allocation-free)
// ---------------------------------------------------------------------------
__device__ float          g_fo[(size_t)Mz * Hz];
__device__ float          g_bo[(size_t)Mz * Hz];
__device__ float          g_x [(size_t)Mz * Hz];
__device__ __nv_bfloat16  g_xhi[(size_t)Mz * Hz];
__device__ __nv_bfloat16  g_xlo[(size_t)Mz * Hz];
// Transposed split weights: [widx=8][jblk=8][nn=256][k=1024]
// nn interleave: for hidden col h' (0..127): nl at (h'>>3)*16 + (h'&7),
//                gate at same + 8.
__device__ __nv_bfloat16  g_Whi[(size_t)8 * 2048 * 1024];
__device__ __nv_bfloat16  g_Wlo[(size_t)8 * 2048 * 1024];

// ---------------------------------------------------------------------------
__global__ void init_kernel(const float* __restrict__ inp) {
    size_t i = (size_t)blockIdx.x * blockDim.x + threadIdx.x;
    float4 v = ((const float4*)inp)[i];
    ((float4*)g_fo)[i] = v;
    ((float4*)g_bo)[i] = v;
}

// ---------------------------------------------------------------------------
// prep_w: transpose + bf16-split + nl/gate 8-col interleave
// widx = dir*4 + l*2 + hw
// ---------------------------------------------------------------------------
__global__ void prep_w_kernel(const float* __restrict__ fw_W,
                              const float* __restrict__ bw_W) {
    int widx = blockIdx.z;
    const float* W = (widx >= 4 ? bw_W : fw_W) +
                     ((size_t)((widx >> 1) & 1) * 2 + (widx & 1)) * Hz * N2;
    __shared__ float tile[32][33];
    int k0 = blockIdx.y * 32, n0 = blockIdx.x * 32;
    int tx = threadIdx.x, ty = threadIdx.y;
#pragma unroll
    for (int i = 0; i < 4; i++) {
        int ky = ty + 8 * i;
        tile[ky][tx] = W[(size_t)(k0 + ky) * N2 + n0 + tx];
    }
    __syncthreads();
#pragma unroll
    for (int i = 0; i < 4; i++) {
        int ny = ty + 8 * i;
        int n = n0 + ny;
        int h = n & 1023;
        int half = n >> 10;           // 0 = nl, 1 = gate
        int jb = h >> 7;
        int hp = h & 127;
        int p = (hp >> 3) * 16 + (hp & 7) + half * 8;
        size_t orow = ((size_t)widx * 2048 + jb * 256 + p) * Hz + k0 + tx;
        float v = tile[tx][ny];
        __nv_bfloat16 hi = __float2bfloat16(v);
        g_Whi[orow] = hi;
        g_Wlo[orow] = __float2bfloat16(v - __bfloat162float(hi));
    }
}

// ---------------------------------------------------------------------------
// window sum -> g_x (float) + g_xhi/g_xlo (bf16 split)
// ---------------------------------------------------------------------------
__global__ void wsum_kernel(const float* __restrict__ pf,
                            const float* __restrict__ pb,
                            const float* __restrict__ w5, int dir) {
    const float* o = dir ? g_bo : g_fo;
    int m  = blockIdx.x;
    int t  = m & (Sz - 1);
    int h4 = threadIdx.x;
    float4 acc = make_float4(0.f, 0.f, 0.f, 0.f);
#pragma unroll
    for (int k = 0; k <= WD; k++) {
        int p = t + k + (dir ? 0 : -WD);
        const float4* src;
        if (p < 0)        src = (const float4*)(pf + (size_t)(p + WD) * Hz);
        else if (p >= Sz) src = (const float4*)(pb + (size_t)(p - Sz) * Hz);
        else              src = (const float4*)(o  + (size_t)(m - t + p) * Hz);
        float wk = w5[k];
        float4 v = src[h4];
        acc.x += wk * v.x; acc.y += wk * v.y;
        acc.z += wk * v.z; acc.w += wk * v.w;
    }
    size_t o4 = (size_t)m * (Hz / 4) + h4;
    ((float4*)g_x)[o4] = acc;
    __nv_bfloat16 h0 = __float2bfloat16(acc.x), h1 = __float2bfloat16(acc.y);
    __nv_bfloat16 h2 = __float2bfloat16(acc.z), h3 = __float2bfloat16(acc.w);
    ((__nv_bfloat162*)g_xhi)[o4 * 2 + 0] = __halves2bfloat162(h0, h1);
    ((__nv_bfloat162*)g_xhi)[o4 * 2 + 1] = __halves2bfloat162(h2, h3);
    ((__nv_bfloat162*)g_xlo)[o4 * 2 + 0] = __halves2bfloat162(
        __float2bfloat16(acc.x - __bfloat162float(h0)),
        __float2bfloat16(acc.y - __bfloat162float(h1)));
    ((__nv_bfloat162*)g_xlo)[o4 * 2 + 1] = __halves2bfloat162(
        __float2bfloat16(acc.z - __bfloat162float(h2)),
        __float2bfloat16(acc.w - __bfloat162float(h3)));
}

// ---------------------------------------------------------------------------
// bf16 mma.sync GEMM + fused highway epilogue.
// CTA: 128 M x 256 (interleaved nl/gate), 512 thr, 16 warps (4 M x 4 N),
// warp tile 32x64, BK=64, 2-stage cp.async pipeline, bf16-split (3 products).
// ---------------------------------------------------------------------------
#define OFF_A   0
#define OFF_ALO 16384
#define OFF_B   32768
#define OFF_BLO 65536
#define STAGE   98304
#define SMEM_BYTES (2 * STAGE)   // 196608

__global__ void __launch_bounds__(512, 1)
gemm_hw_kernel(const float* __restrict__ bias, float* __restrict__ out,
               int widx, int l, int dir, int mode) {
    extern __shared__ char sm[];
    uint32_t sb = smem_to_u32(sm);
    int tid = threadIdx.x, wid = tid >> 5, lane = tid & 31;
    int wy = wid & 3, wx = wid >> 2;
    int jcta = blockIdx.x;
    int m0 = blockIdx.y * 128;
    const size_t wbase = (size_t)widx * 2048 * 1024 + (size_t)jcta * 256 * 1024;

    float acc[2][8][4];
#pragma unroll
    for (int mt = 0; mt < 2; mt++)
#pragma unroll
        for (int j = 0; j < 8; j++)
#pragma unroll
            for (int e = 0; e < 4; e++) acc[mt][j][e] = 0.f;

    // lane-invariant pieces of ldmatrix addresses
    int a_row  = wy * 32 + (lane & 15);           // + mt*16
    int a_colb = (lane >> 4) * 16;                // + ks*32
    int b_row  = wx * 64 + ((lane >> 4) << 3) + (lane & 7);  // + jp*16
    int b_colb = ((lane >> 3) & 1) * 16;          // + ks*32

    // ---- loader lambda-ish macro ----
#define LOAD_STAGE(c, stg) do { \
    int cc = (c); uint32_t so_base = (stg); \
    _Pragma("unroll") \
    for (int i = 0; i < 2; i++) { \
        int idx = tid + 512 * i; int row = idx >> 3, q = idx & 7; \
        size_t g = (size_t)(m0 + row) * Hz + cc * 64 + q * 8; \
        uint32_t so = SW128((uint32_t)(row * 128 + q * 16)); \
        cpasync16(sb + so_base + OFF_A + so, g_xhi + g); \
        cpasync16(sb + so_base + OFF_ALO + so, g_xlo + g); \
    } \
    _Pragma("unroll") \
    for (int i = 0; i < 4; i++) { \
        int idx = tid + 512 * i; int row = idx >> 3, q = idx & 7; \
        size_t g = wbase + (size_t)row * Hz + cc * 64 + q * 8; \
        uint32_t so = SW128((uint32_t)(row * 128 + q * 16)); \
        cpasync16(sb + so_base + OFF_B + so, g_Whi + g); \
        cpasync16(sb + so_base + OFF_BLO + so, g_Wlo + g); \
    } \
    CP_COMMIT(); \
} while (0)

    LOAD_STAGE(0, 0);

    for (int c = 0; c < 16; c++) {
        uint32_t stg = (c & 1) * STAGE;
        if (c + 1 < 16) {
            LOAD_STAGE(c + 1, ((c + 1) & 1) * STAGE);
            CP_WAIT(1);
        } else {
            CP_WAIT(0);
        }
        __syncthreads();

#pragma unroll
        for (int ks = 0; ks < 4; ks++) {
            uint32_t Ah[2][4], Al[2][4];
#pragma unroll
            for (int mt = 0; mt < 2; mt++) {
                uint32_t off = SW128((uint32_t)((a_row + mt * 16) * 128 +
                                                a_colb + ks * 32));
                ldsm4(Ah[mt], sb + stg + OFF_A + off);
                ldsm4(Al[mt], sb + stg + OFF_ALO + off);
            }
            uint32_t Bh[4][4], Bl[4][4];
#pragma unroll
            for (int jp = 0; jp < 4; jp++) {
                uint32_t off = SW128((uint32_t)((b_row + jp * 16) * 128 +
                                                b_colb + ks * 32));
                ldsm4(Bh[jp], sb + stg + OFF_B + off);
                ldsm4(Bl[jp], sb + stg + OFF_BLO + off);
            }
#pragma unroll
            for (int mt = 0; mt < 2; mt++)
#pragma unroll
                for (int jp = 0; jp < 4; jp++) {
                    mma16816(acc[mt][2 * jp],     Ah[mt], Bh[jp] + 0);
                    mma16816(acc[mt][2 * jp + 1], Ah[mt], Bh[jp] + 2);
                    mma16816(acc[mt][2 * jp],     Al[mt], Bh[jp] + 0);
                    mma16816(acc[mt][2 * jp + 1], Al[mt], Bh[jp] + 2);
                    mma16816(acc[mt][2 * jp],     Ah[mt], Bl[jp] + 0);
                    mma16816(acc[mt][2 * jp + 1], Ah[mt], Bl[jp] + 2);
                }
        }
        __syncthreads();
    }

    // ---- fused highway epilogue (in registers) ----
    float* state = dir ? g_bo : g_fo;
#pragma unroll
    for (int mt = 0; mt < 2; mt++) {
        int r0 = m0 + wy * 32 + mt * 16 + (lane >> 2);
#pragma unroll
        for (int p = 0; p < 4; p++) {
            int h = jcta * 128 + wx * 32 + p * 8 + (lane & 3) * 2;
            float bn0 = bias[h],        bn1 = bias[h + 1];
            float bg0 = bias[1024 + h], bg1 = bias[1024 + h + 1];
            const float* nlr = acc[mt][2 * p];
            const float* gr  = acc[mt][2 * p + 1];
#pragma unroll
            for (int hf = 0; hf < 2; hf++) {
                int r = r0 + hf * 8;
                size_t gp = (size_t)r * Hz + h;
                float nl0 = nlr[hf * 2 + 0] + bn0;
                float nl1 = nlr[hf * 2 + 1] + bn1;
                float gg0 = gr[hf * 2 + 0] + bg0;
                float gg1 = gr[hf * 2 + 1] + bg1;
                float gs0 = 1.f / (1.f + __expf(-gg0));
                float gs1 = 1.f / (1.f + __expf(-gg1));
                float2 xo = *(const float2*)(g_x + gp);
                float r0v = gs0 * xo.x + (1.f - gs0) * fmaxf(nl0, 0.f);
                float r1v = gs1 * xo.y + (1.f - gs1) * fmaxf(nl1, 0.f);
                if (mode == 0) {
                    *(float2*)(g_x + gp) = make_float2(r0v, r1v);
                    __nv_bfloat16 b0 = __float2bfloat16(r0v);
                    __nv_bfloat16 b1 = __float2bfloat16(r1v);
                    ((__nv_bfloat162*)g_xhi)[gp / 2] = __halves2bfloat162(b0, b1);
                    ((__nv_bfloat162*)g_xlo)[gp / 2] = __halves2bfloat162(
                        __float2bfloat16(r0v - __bfloat162float(b0)),
                        __float2bfloat16(r1v - __bfloat162float(b1)));
                } else {
                    if (l) {
                        float2 st = *(const float2*)(state + gp);
                        r0v += st.x; r1v += st.y;
                    }
                    *(float2*)(state + gp) = make_float2(r0v, r1v);
                    *(float2*)(out + ((size_t)l * Mz + r) * N2 +
                               (size_t)dir * Hz + h) = make_float2(r0v, r1v);
                }
            }
        }
    }
}

// ---------------------------------------------------------------------------
extern "C" void kernel_launch(void* const* d_in, const int* in_sizes, int n_in,
                              void* d_out, int out_size) {
    const float* inputs = (const float*)d_in[0];
    const float* fw_pad = (const float*)d_in[2];
    const float* bw_pad = (const float*)d_in[3];
    const float* fw_w   = (const float*)d_in[4];
    const float* bw_w   = (const float*)d_in[5];
    const float* fw_W   = (const float*)d_in[6];
    const float* fw_b   = (const float*)d_in[7];
    const float* bw_W   = (const float*)d_in[8];
    const float* bw_b   = (const float*)d_in[9];
    float* out = (float*)d_out;

    cudaFuncSetAttribute(gemm_hw_kernel,
                         cudaFuncAttributeMaxDynamicSharedMemorySize, SMEM_BYTES);

    prep_w_kernel<<<dim3(64, 32, 8), dim3(32, 8)>>>(fw_W, bw_W);
    init_kernel<<<(size_t)Mz * Hz / 4 / 256, 256>>>(inputs);

    for (int l = 0; l < Lz; l++) {
        for (int dir = 0; dir < 2; dir++) {
            const float* bl = (dir ? bw_b : fw_b) + (size_t)l * 2 * N2;
            const float* wv = (dir ? bw_w : fw_w) + (size_t)l * (WD + 1);

            wsum_kernel<<<Mz, 256>>>(fw_pad + (size_t)l * WD * Hz,
                                     bw_pad + (size_t)l * WD * Hz, wv, dir);
            for (int hw = 0; hw < 2; hw++) {
                int widx = dir * 4 + l * 2 + hw;
                gemm_hw_kernel<<<dim3(8, 128), 512, SMEM_BYTES>>>(
                    bl + (size_t)hw * N2, out, widx, l, dir, hw);
            }
        }
    }
}